// round 7
// baseline (speedup 1.0000x reference)
#include <cuda_runtime.h>
#include <cuda_bf16.h>
#include <math.h>

// Problem constants (fixed by the reference)
#define BB 8
#define SS 4096
#define DD 1024
#define HH 16
#define HD 64
#define NR 32
#define NFREQ 32            // HD/2
#define ROWS (BB * SS * HH) // 524288

// Static device scratch (no runtime allocation allowed)
__device__ int    g_rot_i[NR];
__device__ int    g_rot_j[NR];
__device__ float  g_rot_c[NR];
__device__ float  g_rot_s[NR];
__device__ int    g_not_identity;

// ---------------------------------------------------------------------------
// Single setup kernel: identity check (4096 elems) + rotation params.
__global__ void k_setup(const float* __restrict__ thetas,
                        const float* __restrict__ r_pairs,
                        const float* __restrict__ theta_scale,
                        const float* __restrict__ rm) {
    __shared__ int bad;
    int t = threadIdx.x; // 256 threads
    if (t == 0) bad = 0;
    __syncthreads();
    int local = 0;
    #pragma unroll
    for (int e = t; e < HD * HD; e += 256) {
        float expect = ((e >> 6) == (e & 63)) ? 1.0f : 0.0f;
        if (rm[e] != expect) local = 1;
    }
    if (local) bad = 1; // benign race within one block
    __syncthreads();
    if (t == 0) g_not_identity = bad;
    if (t < NR) {
        g_rot_i[t] = (int)r_pairs[2 * t];
        g_rot_j[t] = (int)r_pairs[2 * t + 1];
        float th = thetas[t] * theta_scale[0];
        float sv, cv;
        sincosf(th, &sv, &cv);
        g_rot_c[t] = cv;
        g_rot_s[t] = sv;
    }
}

// ---------------------------------------------------------------------------
// XOR component permute: w[f] = v[f ^ p], p in [0,4)
__device__ __forceinline__ float4 xperm(float4 v, int p) {
    float4 w = v;
    if (p & 1) w = make_float4(w.y, w.x, w.w, w.z);
    if (p & 2) w = make_float4(w.z, w.w, w.x, w.y);
    return w;
}

// Main kernel: 128 threads/block, block covers 128 contiguous rows (32 KB).
// Shared layout: element (row, col) at buf[row*64 + (col ^ (row & 31))].
//  - rotation (per-thread scalar on own row): bank = (col^row)&31 -> conflict-free
//  - staging / epilogue: 16B-aligned accesses with component-XOR permute
#define TPB 128

__global__ void __launch_bounds__(TPB, 6)
k_main(const float* __restrict__ x,
       const float* __restrict__ r_matrix,
       const float* __restrict__ inv_freq,
       float* __restrict__ out) {
    __shared__ float  buf[TPB * HD];      // 32 KB, swizzled
    __shared__ float  rc[NR], rs[NR];
    __shared__ int    ri[NR], rj[NR];

    const int tid = threadIdx.x;
    const int bid = blockIdx.x;
    const long long elem_base = (long long)bid * (TPB * HD);

    // Thread identity for the epilogue (fixed across passes):
    const int l    = tid >> 4;        // s-position within block, 0..7
    const int c4i  = (tid >> 1) & 7;  // frequency quad index, 0..7
    const int rh   = tid & 1;         // row-pairing bit
    const int k0   = c4i * 4;         // freq base, 0..28

    // rotation params -> smem (visible after the first __syncthreads)
    if (tid < NR) {
        ri[tid] = g_rot_i[tid];
        rj[tid] = g_rot_j[tid];
        rc[tid] = g_rot_c[tid];
        rs[tid] = g_rot_s[tid];
    }

    // --- stage input: coalesced float4 -> swizzled smem ---
    const float4* __restrict__ xin = reinterpret_cast<const float4*>(x) + (elem_base >> 2);
    float4* __restrict__ buf4 = reinterpret_cast<float4*>(buf);
    #pragma unroll
    for (int it = 0; it < 16; it++) {
        int g    = tid + it * TPB;          // float4 index in block chunk
        float4 v = __ldcs(&xin[g]);
        int row  = g >> 4;
        int c4   = (g & 15) << 2;
        int r    = row & 31;
        int base = row * 16 + (((c4 ^ (r & 28))) >> 2);
        buf4[base] = xperm(v, r & 3);
    }

    // --- per-thread RoPE cos/sin in registers (4 sincosf, fixed s & freqs) ---
    float csc[4], css[4];
    {
        int s = (bid * 8 + l) & (SS - 1);
        float fs = (float)s;
        #pragma unroll
        for (int m = 0; m < 4; m++) {
            float a = fs * __ldg(&inv_freq[k0 + m]);
            sincosf(a, &css[m], &csc[m]);
        }
    }
    __syncthreads();

    // --- 32 sequential Givens rotations (own row, conflict-free scalar) ---
    {
        const int rbase = tid * HD;
        const int rsw   = tid & 31;
        for (int r = 0; r < NR; r++) {
            int i = ri[r], j = rj[r];
            float c = rc[r], s = rs[r];
            float* pi = &buf[rbase + (i ^ rsw)];
            float* pj = &buf[rbase + (j ^ rsw)];
            float xi = *pi;
            float xj = *pj;
            if (i == j) {
                *pi = xi * c;
            } else {
                *pi = fmaf(xj, s, xi * c);
                *pj = fmaf(xj, c, -xi * s);
            }
        }
    }

    // --- cold generic path: y = y @ r_matrix (skipped when identity) ---
    if (g_not_identity) {
        const int rbase = tid * HD;
        const int rsw   = tid & 31;
        float zl[HD]; // local memory (unroll 1) -> no hot-path registers
        #pragma unroll 1
        for (int c = 0; c < HD; c++) {
            float acc = 0.0f;
            #pragma unroll 1
            for (int k = 0; k < HD; k++)
                acc = fmaf(buf[rbase + (k ^ rsw)], __ldg(&r_matrix[k * HD + c]), acc);
            zl[c] = acc;
        }
        #pragma unroll 1
        for (int c = 0; c < HD; c++)
            buf[rbase + (c ^ rsw)] = zl[c];
    }
    __syncthreads();

    // --- epilogue: each thread reads one 8-float y-block per pass and writes
    //     BOTH its low-half and high-half output float4 (no redundant reads).
    //     Row schedule (h = (p&3) + rh*4 + (p>>2)*8) puts the 4 rows of a warp
    //     on bank-quads {q, q+1, q+4, q+5} -> conflict-free LDS.128. ---
    float4* __restrict__ op = reinterpret_cast<float4*>(out) + (elem_base >> 2);
    const int b8 = 2 * k0;            // y-block start column (8-aligned)
    #pragma unroll
    for (int p = 0; p < 8; p++) {
        int h    = (p & 3) + rh * 4 + ((p >> 2) << 3);
        int row  = l * 16 + h;
        int rsw  = row & 31;
        int qb   = row * 16 + ((b8 ^ (rsw & 24)) >> 2);
        float4 q0 = buf4[qb];
        float4 q1 = buf4[qb + 1];
        int rl = rsw & 7;
        float4 a = (rl & 4) ? q1 : q0;
        float4 b = (rl & 4) ? q0 : q1;
        int pp = rl & 3;
        float4 ya = xperm(a, pp);     // y[b8+0 .. b8+3]
        float4 yb = xperm(b, pp);     // y[b8+4 .. b8+7]

        float4 lo, hi;
        lo.x = fmaf(ya.x, csc[0], -ya.y * css[0]);
        lo.y = fmaf(ya.z, csc[1], -ya.w * css[1]);
        lo.z = fmaf(yb.x, csc[2], -yb.y * css[2]);
        lo.w = fmaf(yb.z, csc[3], -yb.w * css[3]);
        hi.x = fmaf(ya.x, css[0],  ya.y * csc[0]);
        hi.y = fmaf(ya.z, css[1],  ya.w * csc[1]);
        hi.z = fmaf(yb.x, css[2],  yb.y * csc[2]);
        hi.w = fmaf(yb.z, css[3],  yb.w * csc[3]);

        __stcs(&op[row * 16 + c4i], lo);
        __stcs(&op[row * 16 + 8 + c4i], hi);
    }
}

// ---------------------------------------------------------------------------
extern "C" void kernel_launch(void* const* d_in, const int* in_sizes, int n_in,
                              void* d_out, int out_size) {
    const float* x        = (const float*)d_in[0];
    const float* thetas   = (const float*)d_in[1];
    const float* r_pairs  = (const float*)d_in[2];
    const float* t_scale  = (const float*)d_in[3];
    // d_in[4] = n_rots_scale (unused by the reference)
    const float* r_matrix = (const float*)d_in[5];
    const float* inv_freq = (const float*)d_in[6];
    float* out = (float*)d_out;

    k_setup<<<1, 256>>>(thetas, r_pairs, t_scale, r_matrix);

    int nblocks = ROWS / TPB; // 4096
    k_main<<<nblocks, TPB>>>(x, r_matrix, inv_freq, out);
}

// round 8
// speedup vs baseline: 1.3524x; 1.3524x over previous
#include <cuda_runtime.h>
#include <cuda_bf16.h>
#include <math.h>

// Problem constants (fixed by the reference)
#define BB 8
#define SS 4096
#define DD 1024
#define HH 16
#define HD 64
#define NR 32
#define NFREQ 32            // HD/2
#define ROWS (BB * SS * HH) // 524288

// Static device scratch (no runtime allocation allowed)
__device__ int    g_rot_i[NR];
__device__ int    g_rot_j[NR];
__device__ float  g_rot_c[NR];
__device__ float  g_rot_s[NR];
__device__ int    g_not_identity;

// ---------------------------------------------------------------------------
// Single setup kernel: identity check (4096 elems) + rotation params.
__global__ void k_setup(const float* __restrict__ thetas,
                        const float* __restrict__ r_pairs,
                        const float* __restrict__ theta_scale,
                        const float* __restrict__ rm) {
    __shared__ int bad;
    int t = threadIdx.x; // 256 threads
    if (t == 0) bad = 0;
    __syncthreads();
    int local = 0;
    #pragma unroll
    for (int e = t; e < HD * HD; e += 256) {
        float expect = ((e >> 6) == (e & 63)) ? 1.0f : 0.0f;
        if (rm[e] != expect) local = 1;
    }
    if (local) bad = 1; // benign race within one block
    __syncthreads();
    if (t == 0) g_not_identity = bad;
    if (t < NR) {
        g_rot_i[t] = (int)r_pairs[2 * t];
        g_rot_j[t] = (int)r_pairs[2 * t + 1];
        float th = thetas[t] * theta_scale[0];
        float sv, cv;
        sincosf(th, &sv, &cv);
        g_rot_c[t] = cv;
        g_rot_s[t] = sv;
    }
}

// ---------------------------------------------------------------------------
// XOR component permute: w[f] = v[f ^ p], p in [0,4). p is thread-constant in
// all uses -> fixed-predicate SELs after hoisting.
__device__ __forceinline__ float4 xperm(float4 v, int p) {
    float4 w = v;
    if (p & 1) w = make_float4(w.y, w.x, w.w, w.z);
    if (p & 2) w = make_float4(w.z, w.w, w.x, w.y);
    return w;
}

// Main kernel: 128 threads/block, block covers 128 contiguous rows (32 KB).
// Shared layout: element (row, col) at buf[row*64 + (col ^ (row & 31))].
//  - rotation (per-thread scalar on own row): bank = (col^row)&31 -> conflict-free
//  - staging / epilogue: 16B-aligned LDS.128/STS.128, component-XOR permute
#define TPB 128

__global__ void __launch_bounds__(TPB, 6)
k_main(const float* __restrict__ x,
       const float* __restrict__ r_matrix,
       const float* __restrict__ inv_freq,
       float* __restrict__ out) {
    __shared__ float  buf[TPB * HD];      // 32 KB, swizzled
    __shared__ float4 cosq[8][8];         // [s-pos][freq-quad], 512 B
    __shared__ float4 sinq[8][8];         // 512 B
    __shared__ float  rc[NR], rs[NR];
    __shared__ int    ri[NR], rj[NR];

    const int tid = threadIdx.x;
    const int bid = blockIdx.x;
    const long long elem_base = (long long)bid * (TPB * HD);
    const int prow = tid >> 4;            // base row (0..7); also rl = row&7

    // rotation params -> smem
    if (tid < NR) {
        ri[tid] = g_rot_i[tid];
        rj[tid] = g_rot_j[tid];
        rc[tid] = g_rot_c[tid];
        rs[tid] = g_rot_s[tid];
    }
    // cos/sin tables for this block's 8 s-positions (2 sincosf per thread)
    {
        int sg0 = bid * 8;
        #pragma unroll
        for (int e = tid; e < 8 * NFREQ; e += TPB) {
            int l = e >> 5, k = e & 31;
            int s = (sg0 + l) & (SS - 1);
            float a = (float)s * __ldg(&inv_freq[k]);
            float sv, cv;
            sincosf(a, &sv, &cv);
            reinterpret_cast<float*>(&cosq[l][k >> 2])[k & 3] = cv;
            reinterpret_cast<float*>(&sinq[l][k >> 2])[k & 3] = sv;
        }
    }

    // --- stage input: coalesced LDG.128 -> swizzled STS.128 (4-phase clean) ---
    const float4* __restrict__ xin = reinterpret_cast<const float4*>(x) + (elem_base >> 2);
    float4* __restrict__ buf4 = reinterpret_cast<float4*>(buf);
    {
        const int c4 = (tid & 15) << 2;   // constant per thread
        #pragma unroll
        for (int it = 0; it < 16; it++) {
            float4 v = __ldcs(&xin[tid + it * TPB]);
            int row  = prow + it * 8;     // == g>>4
            int r    = row & 31;
            int base = row * 16 + ((c4 ^ (r & 28)) >> 2);
            buf4[base] = xperm(v, r & 3); // r&3 = prow&3, constant
        }
    }
    __syncthreads();

    // --- 32 sequential Givens rotations (own row, conflict-free scalar) ---
    {
        float* __restrict__ my = &buf[tid * HD];
        const int rsw = tid & 31;
        #pragma unroll 4
        for (int r = 0; r < NR; r++) {
            int i = ri[r], j = rj[r];
            float c = rc[r], s = rs[r];
            float* pi = &my[i ^ rsw];
            float* pj = &my[j ^ rsw];
            float xi = *pi;
            float xj = *pj;
            if (i == j) {
                *pi = xi * c;
            } else {
                *pi = fmaf(xj, s, xi * c);
                *pj = fmaf(xj, c, -xi * s);
            }
        }
    }

    // --- cold generic path: y = y @ r_matrix (skipped when identity) ---
    if (g_not_identity) {
        const int rbase = tid * HD;
        const int rsw   = tid & 31;
        float zl[HD]; // local memory (unroll 1) -> no hot-path registers
        #pragma unroll 1
        for (int c = 0; c < HD; c++) {
            float acc = 0.0f;
            #pragma unroll 1
            for (int k = 0; k < HD; k++)
                acc = fmaf(buf[rbase + (k ^ rsw)], __ldg(&r_matrix[k * HD + c]), acc);
            zl[c] = acc;
        }
        #pragma unroll 1
        for (int c = 0; c < HD; c++)
            buf[rbase + (c ^ rsw)] = zl[c];
    }
    __syncthreads();

    // --- fused RoPE + store. STG stays perfectly coalesced: out quad index
    //     q = tid&15 is CONSTANT across iterations (128 % 16 == 0), so each
    //     thread owns fixed freqs; rows advance by 8 per it. ---
    float4* __restrict__ op = reinterpret_cast<float4*>(out) + (elem_base >> 2);
    {
        const int q     = tid & 15;
        const int qp    = q & 7;          // freq-quad 0..7
        const int half  = q >> 3;         // 0: low-half cols, 1: high-half
        const int ldsel = (qp >> 2) & 1;  // load-order trick: full bank-quad cover
        const int rl    = prow;           // row&7, constant across its
        float4 cq, sq;
        #pragma unroll 4
        for (int it = 0; it < 16; it++) {
            int row = prow + it * 8;
            int r   = row & 31;
            if ((it & 1) == 0) {          // l = it>>1 exactly (uniform)
                int l = it >> 1;
                cq = cosq[l][qp];
                sq = sinq[l][qp];
            }
            // y block: logical cols 8qp..8qp+7 live in aligned quads A0, A0+1
            int A0 = row * 16 + (((8 * qp) ^ (r & 24)) >> 2);
            float4 t1 = buf4[A0 + ldsel];
            float4 t2 = buf4[A0 + 1 - ldsel];
            float4 qlo = ldsel ? t2 : t1; // phys floats 0-3 of block
            float4 qhi = ldsel ? t1 : t2; // phys floats 4-7
            float4 a = (rl & 4) ? qhi : qlo;
            float4 b = (rl & 4) ? qlo : qhi;
            float4 ya = xperm(a, rl & 3); // y[8qp+0 .. 8qp+3]
            float4 yb = xperm(b, rl & 3); // y[8qp+4 .. 8qp+7]

            float4 o;
            if (half == 0) {              // out[c] = y0*c - y1*s
                o.x = fmaf(ya.x, cq.x, -ya.y * sq.x);
                o.y = fmaf(ya.z, cq.y, -ya.w * sq.y);
                o.z = fmaf(yb.x, cq.z, -yb.y * sq.z);
                o.w = fmaf(yb.z, cq.w, -yb.w * sq.w);
            } else {                      // out[32+c] = y0*s + y1*c
                o.x = fmaf(ya.x, sq.x, ya.y * cq.x);
                o.y = fmaf(ya.z, sq.y, ya.w * cq.y);
                o.z = fmaf(yb.x, sq.z, yb.y * cq.z);
                o.w = fmaf(yb.z, sq.w, yb.w * cq.w);
            }
            __stcs(&op[tid + it * TPB], o);
        }
    }
}

// ---------------------------------------------------------------------------
extern "C" void kernel_launch(void* const* d_in, const int* in_sizes, int n_in,
                              void* d_out, int out_size) {
    const float* x        = (const float*)d_in[0];
    const float* thetas   = (const float*)d_in[1];
    const float* r_pairs  = (const float*)d_in[2];
    const float* t_scale  = (const float*)d_in[3];
    // d_in[4] = n_rots_scale (unused by the reference)
    const float* r_matrix = (const float*)d_in[5];
    const float* inv_freq = (const float*)d_in[6];
    float* out = (float*)d_out;

    k_setup<<<1, 256>>>(thetas, r_pairs, t_scale, r_matrix);

    int nblocks = ROWS / TPB; // 4096
    k_main<<<nblocks, TPB>>>(x, r_matrix, inv_freq, out);
}

// round 10
// speedup vs baseline: 1.4280x; 1.0559x over previous
#include <cuda_runtime.h>
#include <cuda_bf16.h>
#include <math.h>

// Problem constants (fixed by the reference)
#define BB 8
#define SS 4096
#define DD 1024
#define HH 16
#define HD 64
#define NR 32
#define NFREQ 32            // HD/2
#define ROWS (BB * SS * HH) // 524288
#define TPB 128

// ---------------------------------------------------------------------------
// XOR component permute: w[f] = v[f ^ p], p in [0,4). p thread-constant.
__device__ __forceinline__ float4 xperm(float4 v, int p) {
    float4 w = v;
    if (p & 1) w = make_float4(w.y, w.x, w.w, w.z);
    if (p & 2) w = make_float4(w.z, w.w, w.x, w.y);
    return w;
}

// Single fused kernel. 128 threads/block, 128 rows (32 KB) per block.
// Shared layout: element (row, col) at buf[row*64 + (col ^ (row & 31))]:
//   - scalar rotation on own row: bank = (col^row)&31 -> conflict-free
//   - quad of col c: row*16 + ((c ^ (r&28))>>2), component (c&3)^(r&3)
__global__ void __launch_bounds__(TPB, 6)
k_main(const float* __restrict__ x,
       const float* __restrict__ thetas,
       const float* __restrict__ r_pairs,
       const float* __restrict__ theta_scale,
       const float* __restrict__ r_matrix,
       const float* __restrict__ inv_freq,
       float* __restrict__ out) {
    __shared__ float  buf[TPB * HD];      // 32 KB, swizzled
    __shared__ float4 cosq[8][8];         // [s-pos][freq-quad]
    __shared__ float4 sinq[8][8];
    __shared__ float  rc[NR], rs[NR];
    __shared__ int    ri[NR], rj[NR];

    const int tid = threadIdx.x;
    const int bid = blockIdx.x;
    const long long elem_base = (long long)bid * (TPB * HD);
    float4* __restrict__ buf4 = reinterpret_cast<float4*>(buf);

    // --- rotation params (32 threads, 1 sincosf each) ---
    if (tid < NR) {
        ri[tid] = (int)r_pairs[2 * tid];
        rj[tid] = (int)r_pairs[2 * tid + 1];
        float th = thetas[tid] * theta_scale[0];
        float sv, cv;
        sincosf(th, &sv, &cv);
        rc[tid] = cv;
        rs[tid] = sv;
    }
    // --- RoPE cos/sin tables for this block's 8 s-positions (2 sincosf/thr) ---
    {
        int sg0 = bid * 8;
        #pragma unroll
        for (int e = tid; e < 8 * NFREQ; e += TPB) {
            int l = e >> 5, k = e & 31;
            int s = (sg0 + l) & (SS - 1);
            float a = (float)s * __ldg(&inv_freq[k]);
            float sv, cv;
            sincosf(a, &sv, &cv);
            reinterpret_cast<float*>(&cosq[l][k >> 2])[k & 3] = cv;
            reinterpret_cast<float*>(&sinq[l][k >> 2])[k & 3] = sv;
        }
    }

    // --- stage input: coalesced LDG.128 -> swizzled STS.128 (full unroll) ---
    const float4* __restrict__ xin = reinterpret_cast<const float4*>(x) + (elem_base >> 2);
    {
        const int prow = tid >> 4;
        const int c4   = (tid & 15) << 2;
        const int p    = prow & 3;        // component permute, thread-constant
        #pragma unroll
        for (int it = 0; it < 16; it++) {
            float4 v = __ldcs(&xin[tid + it * TPB]);
            int row  = prow + it * 8;
            int base = row * 16 + ((c4 ^ (row & 28)) >> 2);
            buf4[base] = xperm(v, p);
        }
    }

    // --- identity check for r_matrix (L2-resident 16KB), fused ---
    int local = 0;
    {
        const float4* __restrict__ rm4 = reinterpret_cast<const float4*>(r_matrix);
        #pragma unroll
        for (int m = 0; m < 8; m++) {
            int e4 = tid + m * TPB;       // float4 index, 0..1023
            float4 v = __ldg(&rm4[e4]);
            int rrow = e4 >> 4;
            int c0   = (e4 & 15) << 2;
            if (v.x != ((rrow == c0 + 0) ? 1.0f : 0.0f) ||
                v.y != ((rrow == c0 + 1) ? 1.0f : 0.0f) ||
                v.z != ((rrow == c0 + 2) ? 1.0f : 0.0f) ||
                v.w != ((rrow == c0 + 3) ? 1.0f : 0.0f)) local = 1;
        }
    }
    const int bad = __syncthreads_or(local);  // also fences staging + tables

    // --- 32 sequential Givens rotations (own row, conflict-free scalar) ---
    {
        float* __restrict__ my = &buf[tid * HD];
        const int rsw = tid & 31;
        #pragma unroll 8
        for (int r = 0; r < NR; r++) {
            int i = ri[r], j = rj[r];
            float c = rc[r], s = rs[r];
            float* pi = &my[i ^ rsw];
            float* pj = &my[j ^ rsw];
            float xi = *pi;
            float xj = *pj;
            if (i == j) {
                *pi = xi * c;
            } else {
                *pi = fmaf(xj, s, xi * c);
                *pj = fmaf(xj, c, -xi * s);
            }
        }
    }

    // --- cold generic path: y = y @ r_matrix (own row only, no barrier) ---
    if (bad) {
        const int rbase = tid * HD;
        const int rsw   = tid & 31;
        float zl[HD]; // local memory (unroll 1) -> no hot-path registers
        #pragma unroll 1
        for (int c = 0; c < HD; c++) {
            float acc = 0.0f;
            #pragma unroll 1
            for (int k = 0; k < HD; k++)
                acc = fmaf(buf[rbase + (k ^ rsw)], __ldg(&r_matrix[k * HD + c]), acc);
            zl[c] = acc;
        }
        #pragma unroll 1
        for (int c = 0; c < HD; c++)
            buf[rbase + (c ^ rsw)] = zl[c];
    }
    __syncthreads();

    // --- fused RoPE + store: each thread reads ONE 8-float y-block per pass
    //     and writes BOTH its low-half and high-half output float4.
    //     Lane map: w = warp, sub = (lane>>3), qp = lane&7;
    //     row = 16*it + 4*sub + w  ->  r&3 = w (const permute),
    //     (r&28)>>2 = sub + 4*(it&1) (compile-time shape under full unroll).
    //     Per-warp LDS covers all 8 bank-quads x4 -> 4-phase floor; per-warp
    //     STG.128 covers 4 full 128B sectors -> perfect coalescing. ---
    float4* __restrict__ op = reinterpret_cast<float4*>(out) + (elem_base >> 2);
    {
        const int w   = tid >> 5;         // 0..3
        const int l5  = tid & 31;
        const int sub = l5 >> 3;          // 0..3
        const int qp  = l5 & 7;           // freq-quad 0..7
        #pragma unroll
        for (int it = 0; it < 8; it++) {
            int row  = it * 16 + sub * 4 + w;
            int base = row * 16;
            int qA   = (2 * qp) ^ sub ^ (4 * (it & 1)); // phys quad of col 8qp
            float4 ra = buf4[base + qA];
            float4 rb = buf4[base + (qA ^ 1)];
            float4 ya = xperm(ra, w);     // y[8qp+0 .. 8qp+3]
            float4 yb = xperm(rb, w);     // y[8qp+4 .. 8qp+7]
            float4 cq = cosq[it][qp];     // uniform s-pos = it
            float4 sq = sinq[it][qp];

            float4 lo, hi;                // freqs k = 4qp..4qp+3
            lo.x = fmaf(ya.x, cq.x, -ya.y * sq.x);
            lo.y = fmaf(ya.z, cq.y, -ya.w * sq.y);
            lo.z = fmaf(yb.x, cq.z, -yb.y * sq.z);
            lo.w = fmaf(yb.z, cq.w, -yb.w * sq.w);
            hi.x = fmaf(ya.x, sq.x,  ya.y * cq.x);
            hi.y = fmaf(ya.z, sq.y,  ya.w * cq.y);
            hi.z = fmaf(yb.x, sq.z,  yb.y * cq.z);
            hi.w = fmaf(yb.z, sq.w,  yb.w * cq.w);

            __stcs(&op[base + qp], lo);       // out cols 4qp..4qp+3
            __stcs(&op[base + 8 + qp], hi);   // out cols 32+4qp..32+4qp+3
        }
    }
}

// ---------------------------------------------------------------------------
extern "C" void kernel_launch(void* const* d_in, const int* in_sizes, int n_in,
                              void* d_out, int out_size) {
    const float* x        = (const float*)d_in[0];
    const float* thetas   = (const float*)d_in[1];
    const float* r_pairs  = (const float*)d_in[2];
    const float* t_scale  = (const float*)d_in[3];
    // d_in[4] = n_rots_scale (unused by the reference)
    const float* r_matrix = (const float*)d_in[5];
    const float* inv_freq = (const float*)d_in[6];
    float* out = (float*)d_out;

    int nblocks = ROWS / TPB; // 4096
    k_main<<<nblocks, TPB>>>(x, thetas, r_pairs, t_scale, r_matrix, inv_freq, out);
}

// round 11
// speedup vs baseline: 1.4411x; 1.0092x over previous
#include <cuda_runtime.h>
#include <cuda_bf16.h>
#include <math.h>

// Problem constants (fixed by the reference)
#define BB 8
#define SS 4096
#define DD 1024
#define HH 16
#define HD 64
#define NR 32
#define NFREQ 32            // HD/2
#define ROWS (BB * SS * HH) // 524288
#define TPB 128

// Compile-time XOR component permute: w[f] = v[f ^ P]
template<int P>
__device__ __forceinline__ float4 xperm_c(float4 v) {
    if constexpr (P == 0) return v;
    else if constexpr (P == 1) return make_float4(v.y, v.x, v.w, v.z);
    else if constexpr (P == 2) return make_float4(v.z, v.w, v.x, v.y);
    else                       return make_float4(v.w, v.z, v.y, v.x);
}

// Epilogue specialized on warp index W (compile-time permutes, no SELs).
// Each thread reads one 8-float y-block per pass and writes BOTH output
// halves. Per-warp STG covers 4 full 256B rows -> perfect coalescing.
template<int W>
__device__ __forceinline__ void epilogue(const float4* __restrict__ buf4,
                                         const float4 (*__restrict__ cosq)[8],
                                         const float4 (*__restrict__ sinq)[8],
                                         float4* __restrict__ op,
                                         int sub, int qp) {
    #pragma unroll
    for (int it = 0; it < 8; it++) {
        int row  = it * 16 + sub * 4 + W;
        int base = row * 16;
        int qA   = (2 * qp) ^ sub ^ (4 * (it & 1)); // phys quad of col 8qp
        float4 ra = buf4[base + qA];
        float4 rb = buf4[base + (qA ^ 1)];
        float4 ya = xperm_c<W>(ra);       // y[8qp+0 .. 8qp+3]
        float4 yb = xperm_c<W>(rb);       // y[8qp+4 .. 8qp+7]
        float4 cq = cosq[it][qp];         // s-position = it (uniform)
        float4 sq = sinq[it][qp];

        float4 lo, hi;                    // freqs k = 4qp..4qp+3
        lo.x = fmaf(ya.x, cq.x, -ya.y * sq.x);
        lo.y = fmaf(ya.z, cq.y, -ya.w * sq.y);
        lo.z = fmaf(yb.x, cq.z, -yb.y * sq.z);
        lo.w = fmaf(yb.z, cq.w, -yb.w * sq.w);
        hi.x = fmaf(ya.x, sq.x,  ya.y * cq.x);
        hi.y = fmaf(ya.z, sq.y,  ya.w * cq.y);
        hi.z = fmaf(yb.x, sq.z,  yb.y * cq.z);
        hi.w = fmaf(yb.z, sq.w,  yb.w * cq.w);

        __stcs(&op[base + qp], lo);       // out cols 4qp..4qp+3
        __stcs(&op[base + 8 + qp], hi);   // out cols 32+4qp..32+4qp+3
    }
}

// Single fused kernel. 128 threads/block, 128 rows (32 KB) per block.
// Shared layout: element (row, col) at buf[row*64 + (col ^ (row & 31))]:
//   - scalar access: bank = (col ^ row) & 31 -> conflict-free everywhere
//   - quad of col c: row*16 + ((c>>2) ^ ((row>>2)&7)), component (c&3)^(row&3)
__global__ void __launch_bounds__(TPB, 6)
k_main(const float* __restrict__ x,
       const float* __restrict__ thetas,
       const float* __restrict__ r_pairs,
       const float* __restrict__ theta_scale,
       const float* __restrict__ r_matrix,
       const float* __restrict__ inv_freq,
       float* __restrict__ out) {
    __shared__ float  buf[TPB * HD];      // 32 KB, swizzled
    __shared__ float4 cosq[8][8];         // [s-pos][freq-quad]
    __shared__ float4 sinq[8][8];
    __shared__ float  rc[NR], rs[NR];
    __shared__ int    ri[NR], rj[NR];

    const int tid = threadIdx.x;
    const int bid = blockIdx.x;
    const long long elem_base = (long long)bid * (TPB * HD);
    float4* __restrict__ buf4 = reinterpret_cast<float4*>(buf);

    // --- rotation params (32 threads, 1 sincosf each). s:=0 when i==j makes
    //     the rotation loop branchless. ---
    if (tid < NR) {
        int i = (int)r_pairs[2 * tid];
        int j = (int)r_pairs[2 * tid + 1];
        ri[tid] = i;
        rj[tid] = j;
        float th = thetas[tid] * theta_scale[0];
        float sv, cv;
        sincosf(th, &sv, &cv);
        rc[tid] = cv;
        rs[tid] = (i == j) ? 0.0f : sv;
    }
    // --- RoPE cos/sin tables for this block's 8 s-positions (2 sincosf/thr) ---
    {
        int sg0 = bid * 8;
        #pragma unroll
        for (int e = tid; e < 8 * NFREQ; e += TPB) {
            int l = e >> 5, k = e & 31;
            int s = (sg0 + l) & (SS - 1);
            float a = (float)s * __ldg(&inv_freq[k]);
            float sv, cv;
            sincosf(a, &sv, &cv);
            reinterpret_cast<float*>(&cosq[l][k >> 2])[k & 3] = cv;
            reinterpret_cast<float*>(&sinq[l][k >> 2])[k & 3] = sv;
        }
    }

    // --- stage input: coalesced LDG.128 -> 4 scalar conflict-free STS.32
    //     (zero permute SELs; bank = ((c0+m) ^ row) & 31, distinct per lane) ---
    const float4* __restrict__ xin = reinterpret_cast<const float4*>(x) + (elem_base >> 2);
    {
        const int prow = tid >> 4;
        const int c0   = (tid & 15) << 2;
        #pragma unroll
        for (int it = 0; it < 16; it++) {
            float4 v = __ldcs(&xin[tid + it * TPB]);
            int row = prow + it * 8;
            float* bp = &buf[row * 64];
            int rx = row & 31;
            bp[(c0 + 0) ^ rx] = v.x;
            bp[(c0 + 1) ^ rx] = v.y;
            bp[(c0 + 2) ^ rx] = v.z;
            bp[(c0 + 3) ^ rx] = v.w;
        }
    }

    // --- identity check for r_matrix (L2-resident 16KB), fused ---
    int local = 0;
    {
        const float4* __restrict__ rm4 = reinterpret_cast<const float4*>(r_matrix);
        #pragma unroll
        for (int m = 0; m < 8; m++) {
            int e4 = tid + m * TPB;       // float4 index, 0..1023
            float4 v = __ldg(&rm4[e4]);
            int rrow = e4 >> 4;
            int c0   = (e4 & 15) << 2;
            if (v.x != ((rrow == c0 + 0) ? 1.0f : 0.0f) ||
                v.y != ((rrow == c0 + 1) ? 1.0f : 0.0f) ||
                v.z != ((rrow == c0 + 2) ? 1.0f : 0.0f) ||
                v.w != ((rrow == c0 + 3) ? 1.0f : 0.0f)) local = 1;
        }
    }
    const int bad = __syncthreads_or(local);  // fences staging + tables too

    // --- 32 sequential Givens rotations (own row, conflict-free, branchless) ---
    {
        float* __restrict__ my = &buf[tid * HD];
        const int rsw = tid & 31;
        #pragma unroll 8
        for (int r = 0; r < NR; r++) {
            int ia = ri[r] ^ rsw;
            int ja = rj[r] ^ rsw;
            float c = rc[r], s = rs[r];
            float xi = my[ia];
            float xj = my[ja];
            my[ia] = fmaf(s, xj, c * xi);
            my[ja] = fmaf(c, xj, -s * xi);
        }
    }

    // --- cold generic path: y = y @ r_matrix (own row only, no barrier) ---
    if (bad) {
        const int rbase = tid * HD;
        const int rsw   = tid & 31;
        float zl[HD]; // local memory (unroll 1) -> no hot-path registers
        #pragma unroll 1
        for (int c = 0; c < HD; c++) {
            float acc = 0.0f;
            #pragma unroll 1
            for (int k = 0; k < HD; k++)
                acc = fmaf(buf[rbase + (k ^ rsw)], __ldg(&r_matrix[k * HD + c]), acc);
            zl[c] = acc;
        }
        #pragma unroll 1
        for (int c = 0; c < HD; c++)
            buf[rbase + (c ^ rsw)] = zl[c];
    }
    __syncthreads();

    // --- fused RoPE + store, specialized per warp (uniform switch) ---
    float4* __restrict__ op = reinterpret_cast<float4*>(out) + (elem_base >> 2);
    {
        const int l5  = tid & 31;
        const int sub = l5 >> 3;          // 0..3
        const int qp  = l5 & 7;           // freq-quad 0..7
        switch (tid >> 5) {
            case 0: epilogue<0>(buf4, cosq, sinq, op, sub, qp); break;
            case 1: epilogue<1>(buf4, cosq, sinq, op, sub, qp); break;
            case 2: epilogue<2>(buf4, cosq, sinq, op, sub, qp); break;
            default: epilogue<3>(buf4, cosq, sinq, op, sub, qp); break;
        }
    }
}

// ---------------------------------------------------------------------------
extern "C" void kernel_launch(void* const* d_in, const int* in_sizes, int n_in,
                              void* d_out, int out_size) {
    const float* x        = (const float*)d_in[0];
    const float* thetas   = (const float*)d_in[1];
    const float* r_pairs  = (const float*)d_in[2];
    const float* t_scale  = (const float*)d_in[3];
    // d_in[4] = n_rots_scale (unused by the reference)
    const float* r_matrix = (const float*)d_in[5];
    const float* inv_freq = (const float*)d_in[6];
    float* out = (float*)d_out;

    int nblocks = ROWS / TPB; // 4096
    k_main<<<nblocks, TPB>>>(x, thetas, r_pairs, t_scale, r_matrix, inv_freq, out);
}

// round 12
// speedup vs baseline: 1.4763x; 1.0244x over previous
#include <cuda_runtime.h>
#include <cuda_bf16.h>
#include <math.h>

// Problem constants (fixed by the reference)
#define BB 8
#define SS 4096
#define DD 1024
#define HH 16
#define HD 64
#define NR 32
#define NFREQ 32            // HD/2
#define ROWS (BB * SS * HH) // 524288
#define TPB 128

// Compile-time XOR component permute: w[f] = v[f ^ P]
template<int P>
__device__ __forceinline__ float4 xperm_c(float4 v) {
    if constexpr (P == 0) return v;
    else if constexpr (P == 1) return make_float4(v.y, v.x, v.w, v.z);
    else if constexpr (P == 2) return make_float4(v.z, v.w, v.x, v.y);
    else                       return make_float4(v.w, v.z, v.y, v.x);
}

// Epilogue specialized on warp index W (compile-time permutes, no SELs).
// Each thread reads one 8-float y-block per pass and writes BOTH output
// halves. Per-warp STG covers 4 full 256B rows -> perfect coalescing.
template<int W>
__device__ __forceinline__ void epilogue(const float4* __restrict__ buf4,
                                         const float4 (*__restrict__ cosq)[8],
                                         const float4 (*__restrict__ sinq)[8],
                                         float4* __restrict__ op,
                                         int sub, int qp) {
    #pragma unroll
    for (int it = 0; it < 8; it++) {
        int row  = it * 16 + sub * 4 + W;
        int base = row * 16;
        int qA   = (2 * qp) ^ sub ^ (4 * (it & 1)); // phys quad of col 8qp
        float4 ra = buf4[base + qA];
        float4 rb = buf4[base + (qA ^ 1)];
        float4 ya = xperm_c<W>(ra);       // y[8qp+0 .. 8qp+3]
        float4 yb = xperm_c<W>(rb);       // y[8qp+4 .. 8qp+7]
        float4 cq = cosq[it][qp];         // s-position = it (uniform)
        float4 sq = sinq[it][qp];

        float4 lo, hi;                    // freqs k = 4qp..4qp+3
        lo.x = fmaf(ya.x, cq.x, -ya.y * sq.x);
        lo.y = fmaf(ya.z, cq.y, -ya.w * sq.y);
        lo.z = fmaf(yb.x, cq.z, -yb.y * sq.z);
        lo.w = fmaf(yb.z, cq.w, -yb.w * sq.w);
        hi.x = fmaf(ya.x, sq.x,  ya.y * cq.x);
        hi.y = fmaf(ya.z, sq.y,  ya.w * cq.y);
        hi.z = fmaf(yb.x, sq.z,  yb.y * cq.z);
        hi.w = fmaf(yb.z, sq.w,  yb.w * cq.w);

        __stcs(&op[base + qp], lo);       // out cols 4qp..4qp+3
        __stcs(&op[base + 8 + qp], hi);   // out cols 32+4qp..32+4qp+3
    }
}

// Single fused kernel. 128 threads/block, 128 rows (32 KB) per block.
// Shared layout: element (row, col) at buf[row*64 + (col ^ (row & 31))]:
//   - scalar access: bank = (col ^ row) & 31 -> conflict-free everywhere
//   - quad of col c: row*16 + ((c>>2) ^ ((row>>2)&7)), component (c&3)^(row&3)
__global__ void __launch_bounds__(TPB, 6)
k_main(const float* __restrict__ x,
       const float* __restrict__ thetas,
       const float* __restrict__ r_pairs,
       const float* __restrict__ theta_scale,
       const float* __restrict__ r_matrix,
       const float* __restrict__ inv_freq,
       float* __restrict__ out) {
    __shared__ float  buf[TPB * HD];      // 32 KB, swizzled
    __shared__ float4 cosq[8][8];         // [s-pos][freq-quad]
    __shared__ float4 sinq[8][8];
    __shared__ float  rc[NR], rs[NR];
    __shared__ int    ri[NR], rj[NR];

    const int tid = threadIdx.x;
    const int bid = blockIdx.x;
    const long long elem_base = (long long)bid * (TPB * HD);
    float4* __restrict__ buf4 = reinterpret_cast<float4*>(buf);

    const float4* __restrict__ xin = reinterpret_cast<const float4*>(x) + (elem_base >> 2);
    const int prow = tid >> 4;
    const int c0   = (tid & 15) << 2;

    // ---- chunk 0 loads issued FIRST (4 LDG.128) ----
    float4 v0[4];
    #pragma unroll
    for (int u = 0; u < 4; u++) v0[u] = __ldcs(&xin[tid + u * TPB]);

    // ---- fill chunk-0 load latency with setup work ----
    // rotation params (32 threads, 1 sincosf each); s:=0 when i==j -> branchless
    if (tid < NR) {
        int i = (int)r_pairs[2 * tid];
        int j = (int)r_pairs[2 * tid + 1];
        ri[tid] = i;
        rj[tid] = j;
        float th = thetas[tid] * theta_scale[0];
        float sv, cv;
        sincosf(th, &sv, &cv);
        rc[tid] = cv;
        rs[tid] = (i == j) ? 0.0f : sv;
    }
    // RoPE cos/sin tables for this block's 8 s-positions (2 sincosf/thread)
    {
        int sg0 = bid * 8;
        #pragma unroll
        for (int e = tid; e < 8 * NFREQ; e += TPB) {
            int l = e >> 5, k = e & 31;
            int s = (sg0 + l) & (SS - 1);
            float a = (float)s * __ldg(&inv_freq[k]);
            float sv, cv;
            sincosf(a, &sv, &cv);
            reinterpret_cast<float*>(&cosq[l][k >> 2])[k & 3] = cv;
            reinterpret_cast<float*>(&sinq[l][k >> 2])[k & 3] = sv;
        }
    }
    // identity check for r_matrix (16KB, L1/L2-hot after first blocks)
    int local = 0;
    {
        const float4* __restrict__ rm4 = reinterpret_cast<const float4*>(r_matrix);
        #pragma unroll
        for (int m = 0; m < 8; m++) {
            int e4 = tid + m * TPB;       // float4 index, 0..1023
            float4 v = __ldg(&rm4[e4]);
            int rrow = e4 >> 4;
            int cc   = (e4 & 15) << 2;
            if (v.x != ((rrow == cc + 0) ? 1.0f : 0.0f) ||
                v.y != ((rrow == cc + 1) ? 1.0f : 0.0f) ||
                v.z != ((rrow == cc + 2) ? 1.0f : 0.0f) ||
                v.w != ((rrow == cc + 3) ? 1.0f : 0.0f)) local = 1;
        }
    }

    // ---- store chunk 0, then stream chunks 1..3 with anti-hoist fences.
    //      Caps the front LDG batch at 4 per thread (MLP_p1 16 -> 4) to cut
    //      cross-CTA L1tex-queue contention / CTA completion spread. ----
    #pragma unroll
    for (int u = 0; u < 4; u++) {
        int row = prow + u * 8;
        float* bp = &buf[row * 64];
        int rx = row & 31;
        bp[(c0 + 0) ^ rx] = v0[u].x;
        bp[(c0 + 1) ^ rx] = v0[u].y;
        bp[(c0 + 2) ^ rx] = v0[u].z;
        bp[(c0 + 3) ^ rx] = v0[u].w;
    }
    asm volatile("" ::: "memory");
    #pragma unroll
    for (int ch = 1; ch < 4; ch++) {
        float4 v[4];
        #pragma unroll
        for (int u = 0; u < 4; u++)
            v[u] = __ldcs(&xin[tid + (ch * 4 + u) * TPB]);
        #pragma unroll
        for (int u = 0; u < 4; u++) {
            int it  = ch * 4 + u;
            int row = prow + it * 8;
            float* bp = &buf[row * 64];
            int rx = row & 31;
            bp[(c0 + 0) ^ rx] = v[u].x;
            bp[(c0 + 1) ^ rx] = v[u].y;
            bp[(c0 + 2) ^ rx] = v[u].z;
            bp[(c0 + 3) ^ rx] = v[u].w;
        }
        asm volatile("" ::: "memory");
    }

    const int bad = __syncthreads_or(local);  // fences staging + tables too

    // --- 32 sequential Givens rotations (own row, conflict-free, branchless) ---
    {
        float* __restrict__ my = &buf[tid * HD];
        const int rsw = tid & 31;
        #pragma unroll 8
        for (int r = 0; r < NR; r++) {
            int ia = ri[r] ^ rsw;
            int ja = rj[r] ^ rsw;
            float c = rc[r], s = rs[r];
            float xi = my[ia];
            float xj = my[ja];
            my[ia] = fmaf(s, xj, c * xi);
            my[ja] = fmaf(c, xj, -s * xi);
        }
    }

    // --- cold generic path: y = y @ r_matrix (own row only, no barrier) ---
    if (bad) {
        const int rbase = tid * HD;
        const int rsw   = tid & 31;
        float zl[HD]; // local memory (unroll 1) -> no hot-path registers
        #pragma unroll 1
        for (int c = 0; c < HD; c++) {
            float acc = 0.0f;
            #pragma unroll 1
            for (int k = 0; k < HD; k++)
                acc = fmaf(buf[rbase + (k ^ rsw)], __ldg(&r_matrix[k * HD + c]), acc);
            zl[c] = acc;
        }
        #pragma unroll 1
        for (int c = 0; c < HD; c++)
            buf[rbase + (c ^ rsw)] = zl[c];
    }
    __syncthreads();

    // --- fused RoPE + store, specialized per warp (uniform switch) ---
    float4* __restrict__ op = reinterpret_cast<float4*>(out) + (elem_base >> 2);
    {
        const int l5  = tid & 31;
        const int sub = l5 >> 3;          // 0..3
        const int qp  = l5 & 7;           // freq-quad 0..7
        switch (tid >> 5) {
            case 0: epilogue<0>(buf4, cosq, sinq, op, sub, qp); break;
            case 1: epilogue<1>(buf4, cosq, sinq, op, sub, qp); break;
            case 2: epilogue<2>(buf4, cosq, sinq, op, sub, qp); break;
            default: epilogue<3>(buf4, cosq, sinq, op, sub, qp); break;
        }
    }
}

// ---------------------------------------------------------------------------
extern "C" void kernel_launch(void* const* d_in, const int* in_sizes, int n_in,
                              void* d_out, int out_size) {
    const float* x        = (const float*)d_in[0];
    const float* thetas   = (const float*)d_in[1];
    const float* r_pairs  = (const float*)d_in[2];
    const float* t_scale  = (const float*)d_in[3];
    // d_in[4] = n_rots_scale (unused by the reference)
    const float* r_matrix = (const float*)d_in[5];
    const float* inv_freq = (const float*)d_in[6];
    float* out = (float*)d_out;

    int nblocks = ROWS / TPB; // 4096
    k_main<<<nblocks, TPB>>>(x, thetas, r_pairs, t_scale, r_matrix, inv_freq, out);
}